// round 8
// baseline (speedup 1.0000x reference)
#include <cuda_runtime.h>

// B=2048 rows, N=8192 cols. One CTA per row, 1024 threads x 8 elems.
// Per row: r = |y_true - y_pred|; Newton in beta=1/eps on
// h(beta)=log(sum sinh(beta*r)) - ln(2N) (same unique root as the reference's
// 20 eps-space Newton iterations, converged far past the 1e-3 tolerance):
// 2 warm-start rounds on log(sum e^{beta r}) - ln(2N) (1 exp/elem; at the
// reference init e^{beta0*rmax}=2N so it stays in range and lands ~2% low),
// then full rounds (2 exp/elem) with uniform early exit at |db|<1e-5*beta.
// eps=1/beta (floored), betaF=1/(eps+1e-6) per reference; q=sinh(betaF*r);
// qmax=sinh(betaF*rmax) analytically (sinh monotone on r>=0);
// Lambda' = 0.99*Lambda + 0.1*(0.9*q/(qmax+1e-20) + 0.1);
// loss = mean((Lambda'*r)^2) via per-row partials + tiny second kernel.
// Output: d_out[0] = loss, d_out[1..B*N] = Lambda' (row-major).
//
// Round-8 structure: ONE barrier per solver round. Per-warp partials go to
// double-buffered smem (parity = round counter rc; buffer rc&1 is written
// after barrier rc-1 and read after barrier rc, so reuse at rc+2 is always
// barrier-separated). After the barrier, EVERY warp redundantly reduces the
// 32 partials and EVERY thread redundantly computes the Newton update:
// beta lives in registers (no broadcast var, no serialized t==0 section,
// no sdone flag; the early-exit branch is uniform by construction).

#define BDIM 1024
#define VPT 8

static constexpr int B = 2048;
static constexpr int N = 8192;
static constexpr float LOG_2N = 9.70406052783923f;  // ln(2*N) = ln(16384)

__device__ float g_row_loss[B];

__device__ __forceinline__ float warp_sum(float v) {
#pragma unroll
    for (int o = 16; o; o >>= 1) v += __shfl_xor_sync(0xffffffffu, v, o);
    return v;
}
__device__ __forceinline__ float warp_max(float v) {
#pragma unroll
    for (int o = 16; o; o >>= 1) v = fmaxf(v, __shfl_xor_sync(0xffffffffu, v, o));
    return v;
}

__global__ __launch_bounds__(BDIM)
void custom_loss_row_kernel(const float* __restrict__ y_pred,
                            const float* __restrict__ y_true,
                            const float* __restrict__ Lam,
                            float* __restrict__ out_lambda) {
    const int b = blockIdx.x;
    const size_t base = (size_t)b * N;
    const int t = threadIdx.x;
    const int lane = t & 31;
    const int wid = t >> 5;

    __shared__ float sA[2][32];
    __shared__ float sB[2][32];

    // ---- residuals: float4 loads, 8 elems/thread ----
    const float4* yp4 = (const float4*)(y_pred + base);
    const float4* yt4 = (const float4*)(y_true + base);
    float r[VPT];
    {
        const float4 p0 = yp4[t], g0 = yt4[t];
        r[0] = fabsf(g0.x - p0.x); r[1] = fabsf(g0.y - p0.y);
        r[2] = fabsf(g0.z - p0.z); r[3] = fabsf(g0.w - p0.w);
        const float4 p1 = yp4[t + BDIM], g1 = yt4[t + BDIM];
        r[4] = fabsf(g1.x - p1.x); r[5] = fabsf(g1.y - p1.y);
        r[6] = fabsf(g1.z - p1.z); r[7] = fabsf(g1.w - p1.w);
    }

    // ---- round 0: row max(r), 1 barrier, redundant cross-warp reduce ----
    float m = r[0];
#pragma unroll
    for (int i = 1; i < VPT; i++) m = fmaxf(m, r[i]);
    m = warp_max(m);
    if (lane == 0) sA[0][wid] = m;
    __syncthreads();
    const float rmax = warp_max(sA[0][lane]);  // uniform across block

    // beta0 = 1/eps0, eps0 = max(rmax,1e-8)/(ln(2N)+1e-8)  (reference init)
    float beta = (LOG_2N + 1e-8f) / fmaxf(rmax, 1e-8f);

    int rc = 1;  // round counter (round 0 was rowmax, used buffer 0)

    // ---- rounds 1-2: warm start on sum(e^{beta r}) = 2N (1 exp/elem) ----
    // True root satisfies sum(e^x) = 2N + sum(e^-x); the warm root sits ~2%
    // below it; monotone decreasing from beta0 (e^{beta0*rmax} = 2N).
#pragma unroll 1
    for (int w = 0; w < 2; w++, rc++) {
        float S = 0.0f, T = 0.0f;
#pragma unroll
        for (int i = 0; i < VPT; i++) {
            const float E = __expf(beta * r[i]);
            S += E;
            T = fmaf(E, r[i], T);
        }
        S = warp_sum(S);
        T = warp_sum(T);
        const int pb = rc & 1;
        if (lane == 0) { sA[pb][wid] = S; sB[pb][wid] = T; }
        __syncthreads();
        const float S2 = warp_sum(sA[pb][lane]);   // all warps, uniform
        const float T2 = warp_sum(sB[pb][lane]);
        const float h  = __logf(S2) - LOG_2N;
        const float db = h * __fdividef(S2, T2);
        beta = fminf(fmaxf(beta - db, 0.05f * beta), 4.0f * beta);
    }

    // ---- full Newton on h(beta)=log(S)-ln(2N), S = sum(e^x - e^-x) ----
#pragma unroll 1
    for (int itn = 0; itn < 8; itn++, rc++) {
        float S = 0.0f, T = 0.0f;
#pragma unroll
        for (int i = 0; i < VPT; i++) {
            const float x  = beta * r[i];
            const float E  = __expf(x);
            const float Em = __expf(-x);
            S += (E - Em);
            T = fmaf(E + Em, r[i], T);
        }
        S = warp_sum(S);
        T = warp_sum(T);
        const int pb = rc & 1;
        if (lane == 0) { sA[pb][wid] = S; sB[pb][wid] = T; }
        __syncthreads();
        const float S2 = warp_sum(sA[pb][lane]);
        const float T2 = warp_sum(sB[pb][lane]);
        const float h  = __logf(S2) - LOG_2N;
        const float db = h * __fdividef(S2, T2);
        const bool done = fabsf(db) < 1e-5f * beta;   // uniform
        beta = fminf(fmaxf(beta - db, 0.05f * beta), 4.0f * beta);
        if (done) break;
    }

    // ---- final beta exactly as reference: eps floor, then +1e-6 ----
    const float eps = fmaxf(__fdividef(1.0f, beta), 1e-8f);
    const float betaF = __fdividef(1.0f, eps + 1e-6f);

    // qmax analytically: sinh monotone on r>=0 -> max at rmax
    const float xm = betaF * rmax;
    const float qmax = 0.5f * (__expf(xm) - __expf(-xm));
    const float inv_qm = __fdividef(1.0f, qmax + 1e-20f);

    // ---- q, Lambda update, per-row loss partial ----
    // (float4 Lambda loads; scalar stores: out base is +1 float, misaligned)
    const float4* L4 = (const float4*)(Lam + base);
    float lsum = 0.0f;
    {
        const float4 l0 = L4[t];
        const float la0[4] = {l0.x, l0.y, l0.z, l0.w};
#pragma unroll
        for (int i = 0; i < 4; i++) {
            const float x  = betaF * r[i];
            const float q  = 0.5f * (__expf(x) - __expf(-x));
            const float qn = q * inv_qm;
            const float lam = fmaf(0.99f, la0[i], 0.1f * fmaf(0.9f, qn, 0.1f));
            out_lambda[base + 4 * t + i] = lam;
            const float z = lam * r[i];
            lsum = fmaf(z, z, lsum);
        }
        const float4 l1 = L4[t + BDIM];
        const float la1[4] = {l1.x, l1.y, l1.z, l1.w};
#pragma unroll
        for (int i = 0; i < 4; i++) {
            const float x  = betaF * r[4 + i];
            const float q  = 0.5f * (__expf(x) - __expf(-x));
            const float qn = q * inv_qm;
            const float lam = fmaf(0.99f, la1[i], 0.1f * fmaf(0.9f, qn, 0.1f));
            out_lambda[base + 4 * (t + BDIM) + i] = lam;
            const float z = lam * r[4 + i];
            lsum = fmaf(z, z, lsum);
        }
    }

    // ---- loss partial: use buffer (rc+1)&1 — not touched by the last
    //      completed round rc, and its round-(rc-1) readers finished before
    //      barrier rc, so this write is barrier-separated from all readers.
    lsum = warp_sum(lsum);
    const int pb2 = (rc + 1) & 1;
    if (lane == 0) sA[pb2][wid] = lsum;
    __syncthreads();
    if (t == 0) {
        float v = 0.0f;
#pragma unroll
        for (int i = 0; i < 32; i++) v += sA[pb2][i];
        g_row_loss[b] = v;
    }
}

__global__ void loss_reduce_kernel(float* __restrict__ out_loss) {
    const int t = threadIdx.x;  // 1024 threads
    float s = g_row_loss[t] + g_row_loss[t + 1024];
    s = warp_sum(s);
    __shared__ float sm[32];
    if ((t & 31) == 0) sm[t >> 5] = s;
    __syncthreads();
    if (t < 32) {
        float v = warp_sum(sm[t]);
        if (t == 0) out_loss[0] = v * (1.0f / 16777216.0f);  // / (B*N)
    }
}

extern "C" void kernel_launch(void* const* d_in, const int* in_sizes, int n_in,
                              void* d_out, int out_size) {
    const float* y_pred = (const float*)d_in[0];
    const float* y_true = (const float*)d_in[1];
    const float* Lam    = (const float*)d_in[2];
    // d_in[3] = it (unused by the cosh branch)

    float* out = (float*)d_out;       // out[0] = loss
    float* out_lambda = out + 1;      // out[1..] = updated Lambda

    custom_loss_row_kernel<<<B, BDIM>>>(y_pred, y_true, Lam, out_lambda);
    loss_reduce_kernel<<<1, 1024>>>(out);
}